// round 4
// baseline (speedup 1.0000x reference)
#include <cuda_runtime.h>
#include <cuda_bf16.h>

// Problem shape (fixed by the reference)
#define BB 16
#define TT 4096
#define HH 512
#define SS 64            // T-chunks per batch
#define TC (TT / SS)     // 64 rows per chunk
#define H4 (HH / 4)      // 128 float4 per row

// Scratch: per (b, chunk): 512 global-sum + 512 local-sum floats (4 MiB, L2-resident)
__device__ float g_partial[BB * SS * 2 * HH];
__device__ int   g_counts[BB * SS];
__device__ int   g_done[BB];             // zero-init; last CTA resets -> replayable

// One fused kernel. Each CTA: stream one (b, t-chunk) of 64 rows x 2 KiB
// (coalesced float4, streaming loads), write partials to scratch, then the
// LAST-finishing CTA of each batch reduces the 64 partials and writes out.
__global__ __launch_bounds__(128) void pool_kernel(
    const float4* __restrict__ x,
    const int* __restrict__ lengths,
    const int* __restrict__ mask,        // jax bool materialized as int32
    float* __restrict__ out)
{
    const int blk = blockIdx.x;          // 0 .. B*S-1
    const int b   = blk / SS;
    const int s   = blk % SS;
    const int tid = threadIdx.x;         // 0..127

    const int L  = lengths[b];
    const int t0 = s * TC;

    const float4* __restrict__ xp = x + (size_t)b * TT * H4 + (size_t)t0 * H4 + tid;
    const int* __restrict__ mp = mask + (size_t)b * TT + t0;

    float4 ag = make_float4(0.f, 0.f, 0.f, 0.f);
    float4 al = make_float4(0.f, 0.f, 0.f, 0.f);
    int cnt = 0;

    #pragma unroll 8
    for (int t = 0; t < TC; ++t) {
        float4 v = __ldcs(&xp[(size_t)t * H4]);
        bool g = (t0 + t) < L;           // warp-uniform
        bool m = (mp[t] != 0);           // warp-uniform broadcast
        if (g) { ag.x += v.x; ag.y += v.y; ag.z += v.z; ag.w += v.w; }
        if (m) { al.x += v.x; al.y += v.y; al.z += v.z; al.w += v.w; cnt++; }
    }

    // Write this chunk's partials to scratch (plain stores; land in L2).
    float4* outp = reinterpret_cast<float4*>(g_partial) + (size_t)blk * (2 * HH / 4);
    outp[tid]      = ag;
    outp[H4 + tid] = al;
    if (tid == 0) g_counts[blk] = cnt;

    // ---- last-CTA-per-batch fused finalize ----
    __shared__ int is_last;
    __threadfence();                     // make partials visible GPU-wide
    if (tid == 0) {
        int v = atomicAdd(&g_done[b], 1);
        is_last = (v == SS - 1);
    }
    __syncthreads();
    if (!is_last) return;

    // This CTA is the 64th arriver for batch b: reduce 64 x 1024 partials.
    // Thread tid owns float4 lanes q = tid (global half) and q+128 (local half).
    const float4* pbase = reinterpret_cast<const float4*>(g_partial)
                        + (size_t)b * SS * (2 * HH / 4);
    float4 sg = make_float4(0.f, 0.f, 0.f, 0.f);
    float4 sl = make_float4(0.f, 0.f, 0.f, 0.f);
    #pragma unroll 8
    for (int c = 0; c < SS; ++c) {
        float4 a = pbase[(size_t)c * (2 * HH / 4) + tid];
        float4 d = pbase[(size_t)c * (2 * HH / 4) + H4 + tid];
        sg.x += a.x; sg.y += a.y; sg.z += a.z; sg.w += a.w;
        sl.x += d.x; sl.y += d.y; sl.z += d.z; sl.w += d.w;
    }

    int tot = 0;
    #pragma unroll 8
    for (int c = 0; c < SS; ++c) tot += g_counts[b * SS + c];   // broadcast loads

    const float dg = 1.0f / (float)(L  > 1 ? L  : 1);
    const float dl = 1.0f / (float)(tot > 1 ? tot : 1);

    float4* o4 = reinterpret_cast<float4*>(out) + (size_t)b * (2 * HH / 4);
    o4[tid]      = make_float4(sg.x * dg, sg.y * dg, sg.z * dg, sg.w * dg);
    o4[H4 + tid] = make_float4(sl.x * dl, sl.y * dl, sl.z * dl, sl.w * dl);

    if (tid == 0) g_done[b] = 0;         // reset for next graph replay
}

extern "C" void kernel_launch(void* const* d_in, const int* in_sizes, int n_in,
                              void* d_out, int out_size)
{
    const float4* x       = (const float4*)d_in[0];   // [B,T,H] f32
    const int*    lengths = (const int*)d_in[1];      // [B] i32
    const int*    mask    = (const int*)d_in[2];      // [B,T] bool -> i32
    float*        out     = (float*)d_out;            // [B, 2H] f32

    pool_kernel<<<BB * SS, 128>>>(x, lengths, mask, out);
}

// round 5
// speedup vs baseline: 1.1769x; 1.1769x over previous
#include <cuda_runtime.h>
#include <cuda_bf16.h>

// Problem shape (fixed by the reference)
#define BB 16
#define TT 4096
#define HH 512
#define SS 64            // T-chunks per batch
#define TC (TT / SS)     // 64 rows per chunk
#define H4 (HH / 4)      // 128 float4 per row
#define P2 8             // pass-2 column-splits per batch

// Scratch: per (b, chunk): 512 global-sum + 512 local-sum floats (4 MiB)
__device__ float g_partial[BB * SS * 2 * HH];
__device__ int   g_counts[BB * SS];

// Pass 1: each CTA handles one (b, t-chunk); 128 threads x float4 cover H=512.
// Streams 64 rows of 2 KiB coalesced. __ldcs marks the 128 MiB stream
// evict-first so the 4 MiB partials (normal policy) stay L2-resident for pass 2.
__global__ __launch_bounds__(128) void pass1_kernel(
    const float4* __restrict__ x,
    const int* __restrict__ lengths,
    const int* __restrict__ mask)      // jax bool materialized as int32
{
    const int blk = blockIdx.x;          // 0 .. B*S-1
    const int b   = blk / SS;
    const int s   = blk % SS;
    const int tid = threadIdx.x;         // 0..127

    const int L  = lengths[b];
    const int t0 = s * TC;

    const float4* __restrict__ xp = x + (size_t)b * TT * H4 + (size_t)t0 * H4 + tid;
    const int* __restrict__ mp = mask + (size_t)b * TT + t0;

    float4 ag = make_float4(0.f, 0.f, 0.f, 0.f);
    float4 al = make_float4(0.f, 0.f, 0.f, 0.f);
    int cnt = 0;

    #pragma unroll 8
    for (int t = 0; t < TC; ++t) {
        float4 v = __ldcs(&xp[(size_t)t * H4]);
        bool g = (t0 + t) < L;           // warp-uniform
        bool m = (mp[t] != 0);           // warp-uniform broadcast
        if (g) { ag.x += v.x; ag.y += v.y; ag.z += v.z; ag.w += v.w; }
        if (m) { al.x += v.x; al.y += v.y; al.z += v.z; al.w += v.w; cnt++; }
    }

    float4* outp = reinterpret_cast<float4*>(g_partial) + (size_t)blk * (2 * HH / 4);
    outp[tid]      = ag;
    outp[H4 + tid] = al;
    if (tid == 0) g_counts[blk] = cnt;
}

// Pass 2: 128 CTAs (16 batches x 8 column-splits) x 128 threads.
// Thread owns one of the 1024 output columns of its batch-eighth; reads the
// 64 chunk partials (coalesced 512B per chunk per CTA, mostly L2 hits).
__global__ __launch_bounds__(128) void pass2_kernel(
    const int* __restrict__ lengths,
    float* __restrict__ out)
{
    const int b    = blockIdx.x / P2;
    const int part = blockIdx.x % P2;
    const int h    = part * (2 * HH / P2) + threadIdx.x;   // 0..1023

    const float* p = g_partial + (size_t)b * SS * (2 * HH) + h;
    float sum = 0.f;
    #pragma unroll 8
    for (int c = 0; c < SS; ++c)
        sum += p[(size_t)c * (2 * HH)];

    int tot = 0;
    #pragma unroll 8
    for (int c = 0; c < SS; ++c) tot += g_counts[b * SS + c];  // broadcast loads

    const int L = lengths[b];
    const float denom = (h < HH) ? (float)(L   > 1 ? L   : 1)
                                 : (float)(tot > 1 ? tot : 1);

    out[(size_t)b * 2 * HH + h] = sum / denom;
}

extern "C" void kernel_launch(void* const* d_in, const int* in_sizes, int n_in,
                              void* d_out, int out_size)
{
    const float4* x       = (const float4*)d_in[0];   // [B,T,H] f32
    const int*    lengths = (const int*)d_in[1];      // [B] i32
    const int*    mask    = (const int*)d_in[2];      // [B,T] bool -> i32
    float*        out     = (float*)d_out;            // [B, 2H] f32

    pass1_kernel<<<BB * SS, 128>>>(x, lengths, mask);
    pass2_kernel<<<BB * P2, 128>>>(lengths, out);
}

// round 6
// speedup vs baseline: 1.2554x; 1.0667x over previous
#include <cuda_runtime.h>
#include <cuda_bf16.h>

// Problem shape (fixed by the reference)
#define BB 16
#define TT 4096
#define HH 512
#define SS 64            // T-chunks per batch
#define TC (TT / SS)     // 64 rows per chunk
#define H4 (HH / 4)      // 128 float4 per row
#define CP 8             // pass-2 chunk-splits  (SS/CP = 8 chunks per thread)
#define COLP 8           // pass-2 column-splits (1024 cols / 128 threads)

// Scratch: per (b, chunk): 512 global-sum + 512 local-sum floats (4 MiB)
__device__ float g_partial[BB * SS * 2 * HH];
__device__ int   g_counts[BB * SS];

// Pass 1: each CTA handles one (b, t-chunk); 128 threads x float4 cover H=512.
// Streams 64 rows of 2 KiB coalesced (evict-first). First 32 CTAs also zero
// the output buffer so pass-2 can accumulate into it with atomics.
__global__ __launch_bounds__(128) void pass1_kernel(
    const float4* __restrict__ x,
    const int* __restrict__ lengths,
    const int* __restrict__ mask,        // jax bool materialized as int32
    float4* __restrict__ out4)           // [B*2H/4] — zeroed here
{
    const int blk = blockIdx.x;          // 0 .. B*S-1
    const int b   = blk / SS;
    const int s   = blk % SS;
    const int tid = threadIdx.x;         // 0..127

    // Zero out[] (16K floats = 4K float4) across the first 32 CTAs.
    if (blk < 32) out4[blk * 128 + tid] = make_float4(0.f, 0.f, 0.f, 0.f);

    const int L  = lengths[b];
    const int t0 = s * TC;

    const float4* __restrict__ xp = x + (size_t)b * TT * H4 + (size_t)t0 * H4 + tid;
    const int* __restrict__ mp = mask + (size_t)b * TT + t0;

    float4 ag = make_float4(0.f, 0.f, 0.f, 0.f);
    float4 al = make_float4(0.f, 0.f, 0.f, 0.f);
    int cnt = 0;

    #pragma unroll 8
    for (int t = 0; t < TC; ++t) {
        float4 v = __ldcs(&xp[(size_t)t * H4]);
        bool g = (t0 + t) < L;           // warp-uniform
        bool m = (mp[t] != 0);           // warp-uniform broadcast
        if (g) { ag.x += v.x; ag.y += v.y; ag.z += v.z; ag.w += v.w; }
        if (m) { al.x += v.x; al.y += v.y; al.z += v.z; al.w += v.w; cnt++; }
    }

    float4* outp = reinterpret_cast<float4*>(g_partial) + (size_t)blk * (2 * HH / 4);
    outp[tid]      = ag;
    outp[H4 + tid] = al;
    if (tid == 0) g_counts[blk] = cnt;
}

// Pass 2: 1024 CTAs = (b, colpart, chunkpart); 128 threads. Each thread sums
// 8 chunk-partials for one output column, pre-divides by the denominator, and
// atomically accumulates into out (zeroed by pass-1).
__global__ __launch_bounds__(128) void pass2_kernel(
    const int* __restrict__ lengths,
    float* __restrict__ out)
{
    const int blk       = blockIdx.x;
    const int b         = blk / (COLP * CP);
    const int colpart   = (blk / CP) % COLP;
    const int chunkpart = blk % CP;
    const int h         = colpart * 128 + threadIdx.x;     // 0..1023

    const int c0 = chunkpart * (SS / CP);
    const float* p = g_partial + ((size_t)b * SS + c0) * (2 * HH) + h;

    float sum = 0.f;
    #pragma unroll
    for (int c = 0; c < SS / CP; ++c)
        sum += p[(size_t)c * (2 * HH)];

    float denom;
    if (h < HH) {
        const int L = lengths[b];
        denom = (float)(L > 1 ? L : 1);
    } else {
        int tot = 0;
        #pragma unroll 8
        for (int c = 0; c < SS; ++c) tot += g_counts[b * SS + c];  // broadcast
        denom = (float)(tot > 1 ? tot : 1);
    }

    atomicAdd(&out[(size_t)b * 2 * HH + h], sum / denom);
}

extern "C" void kernel_launch(void* const* d_in, const int* in_sizes, int n_in,
                              void* d_out, int out_size)
{
    const float4* x       = (const float4*)d_in[0];   // [B,T,H] f32
    const int*    lengths = (const int*)d_in[1];      // [B] i32
    const int*    mask    = (const int*)d_in[2];      // [B,T] bool -> i32
    float*        out     = (float*)d_out;            // [B, 2H] f32

    pass1_kernel<<<BB * SS, 128>>>(x, lengths, mask, (float4*)out);
    pass2_kernel<<<BB * COLP * CP, 128>>>(lengths, out);
}